// round 13
// baseline (speedup 1.0000x reference)
#include <cuda_runtime.h>
#include <cstdint>

#define NB 8
#define NA 49104
#define NC 90
#define IMGF 512.0f
#define SCORE_THR 0.2f
#define THR_BITS 0x3E4CCCCDu   /* bits of 0.2f; valid <=> bits > THR_BITS */
#define FINE_CUT 0x3F7F0000u   /* ~0.99609: fine-bin region start */
#define STATIC_CUT 0x3F7FE000u /* fine bin 896; list pre-filter cut (~0.99951) */
#define NCOARSE 9799
#define NFINE 1024
#define NBINS (NCOARSE + NFINE)   /* 10823 */
#define BINS_PT 11
#define IOU_THR 0.2f
#define K_PRE 1000
#define K_OUT 100
#define NROW (NB * NA)
#define CAND_CAP 2048
#define M_FAST 192
#define GCAP 4096
#define TR 128                  /* rows per k_maxarg block */

typedef unsigned long long ull;

// -------- scratch (zero-init at load; k_fused re-zeroes g_hist/g_gcnt) -----
__device__ float g_maxs[NROW];
__device__ unsigned char g_cls[NROW];
__device__ int g_hist[NB * NBINS];
__device__ int g_gcnt[NB];
__device__ ull g_list[NB * GCAP];

__device__ __forceinline__ unsigned bin_floor(int bin) {
    return (bin >= NCOARSE) ? FINE_CUT + ((unsigned)(bin - NCOARSE) << 6)
                            : THR_BITS + ((unsigned)bin << 11);
}

// ---- K1: coalesced smem staging + quad-per-row reduce (512 thr, full occ) --
__global__ void __launch_bounds__(512) k_maxarg(const float* __restrict__ cls) {
    __shared__ float s[TR * NC];                  // 46080 B static
    const int blk = blockIdx.x, tid = threadIdx.x;

    // stage 128 rows = 2880 float4, fully coalesced, 512 threads
    const float4* src = reinterpret_cast<const float4*>(cls + (size_t)blk * TR * NC);
    float4* dst = reinterpret_cast<float4*>(s);
#pragma unroll
    for (int i = 0; i < 6; i++) {
        int k = tid + i * 512;
        if (k < TR * NC / 4) dst[k] = src[k];
    }
    __syncthreads();

    // reduce: quad (4 threads) per row; thread q owns float2 [q*12, q*12+11]
    const int r = tid >> 2, q = tid & 3;
    const float2* p = reinterpret_cast<const float2*>(s + r * NC) + q * 12;
    const int n2 = (q == 3) ? 9 : 12;             // 12+12+12+9 = 45 float2

    unsigned b0 = 0, b1 = 0;
    int j0 = 0, j1 = 1;
    const int ebase = q * 24;
#pragma unroll
    for (int i = 0; i < 12; i++) {
        if (i < n2) {
            float2 a = p[i];
            unsigned u0 = __float_as_uint(a.x), u1 = __float_as_uint(a.y);
            if (u0 > b0) { b0 = u0; j0 = ebase + 2 * i; }
            if (u1 > b1) { b1 = u1; j1 = ebase + 2 * i + 1; }
        }
    }
    // pack key = (bits<<32) | (89 - idx): max key == max score, min index on tie
    ull k0 = ((ull)b0 << 32) | (unsigned)(89 - j0);
    ull k1 = ((ull)b1 << 32) | (unsigned)(89 - j1);
    ull key = k0 > k1 ? k0 : k1;
    {   // merge the quad (groups are lane-aligned, xor stays in-group)
        ull o = __shfl_xor_sync(0xffffffffu, key, 1);
        if (o > key) key = o;
        o = __shfl_xor_sync(0xffffffffu, key, 2);
        if (o > key) key = o;
    }
    if (q == 0) {
        const int row = blk * TR + r;
        unsigned mx = (unsigned)(key >> 32);
        int bi = 89 - (int)(key & 0xFFu);
        g_maxs[row] = __uint_as_float(mx);
        g_cls[row] = (unsigned char)bi;
        if (mx > THR_BITS) {
            int b = row / NA;
            unsigned bin = (mx >= FINE_CUT)
                             ? (unsigned)NCOARSE + min((mx - FINE_CUT) >> 6, (unsigned)(NFINE - 1))
                             : (mx - THR_BITS) >> 11;
            atomicAdd(&g_hist[b * NBINS + bin], 1);
            if (mx >= STATIC_CUT) {
                int idx = row - b * NA;
                int pos = atomicAdd(&g_gcnt[b], 1);
                if (pos < GCAP)
                    g_list[b * GCAP + pos] = ((ull)mx << 32) |
                                             ((ull)(0xFFFFu - (unsigned)idx) << 16) | (ull)bi;
            }
        }
    }
}

// ---------------- K2: fused thresholds + compact + sort + bucketed NMS -----
__global__ void __launch_bounds__(1024, 1)
k_fused(const float* __restrict__ loc,
        const float* __restrict__ anchors,
        float* __restrict__ out) {
    const int b = blockIdx.x;
    const int tid = threadIdx.x;
    const int lane = tid & 31, w = tid >> 5;
    const int NT = 1024;

    __shared__ ull buf[CAND_CAP];           // sort keys; reused as adj after decode
    __shared__ float4 sbox[1024];
    __shared__ float sval[1024];
    __shared__ int scls[1024];
    __shared__ float4 kbox[K_OUT];
    __shared__ float karea[K_OUT];
    __shared__ int kcls[K_OUT];
    __shared__ short kept[K_OUT];
    __shared__ int wtot[32];
    __shared__ int s_nk, s_cnt, s_gc, s_K;
    __shared__ unsigned s_thr[2];
    __shared__ int s_ccnt[96], s_cstart[96], s_coff[96];
    __shared__ short s_clist[256];

    unsigned* adj = reinterpret_cast<unsigned*>(buf);   // adj[i*8 + word], 256x8

    int* h = g_hist + b * NBINS;
    if (tid == 0) {
        s_gc = g_gcnt[b];
        s_thr[0] = 0xFFFFFFFFu; s_thr[1] = 0xFFFFFFFFu;
        s_nk = 0; s_K = 0;
    }

    // ---- fast threshold pass: fine region only, coalesced ----
    int fineval = h[NBINS - 1 - tid];       // tid t owns fine bin NBINS-1-t (desc)
    int ps = fineval;
#pragma unroll
    for (int off = 1; off < 32; off <<= 1) {
        int t2 = __shfl_up_sync(0xffffffffu, ps, off);
        if (lane >= off) ps += t2;
    }
    if (lane == 31) wtot[w] = ps;
    __syncthreads();
    if (w == 0) {
        int v = wtot[lane];
#pragma unroll
        for (int off = 1; off < 32; off <<= 1) {
            int t2 = __shfl_up_sync(0xffffffffu, v, off);
            if (lane >= off) v += t2;
        }
        wtot[lane] = v;
    }
    __syncthreads();
    const int fine_total = wtot[31];
    bool fine_ok = (fine_total >= K_PRE);
    int K;
    if (fine_ok) {
        K = K_PRE;
        int above = (ps - fineval) + (w > 0 ? wtot[w - 1] : 0);
        const int m = M_FAST;
#pragma unroll
        for (int t2 = 0; t2 < 2; t2++) {
            int r = (t2 == 0) ? m : K_PRE;
            if (above < r && r <= above + fineval)
                s_thr[t2] = FINE_CUT + ((unsigned)(1023 - tid) << 6);
        }
        if (tid == 0) s_K = K_PRE;
        __syncthreads();
    } else {
        __syncthreads();
        int loc10[BINS_PT];
        int ssum = 0;
#pragma unroll
        for (int j = 0; j < BINS_PT; j++) {
            int bi = NBINS - 1 - (tid * BINS_PT + j);
            loc10[j] = (bi >= 0) ? h[bi] : 0;
            ssum += loc10[j];
        }
        int ps2 = ssum;
#pragma unroll
        for (int off = 1; off < 32; off <<= 1) {
            int t2 = __shfl_up_sync(0xffffffffu, ps2, off);
            if (lane >= off) ps2 += t2;
        }
        if (lane == 31) wtot[w] = ps2;
        __syncthreads();
        if (w == 0) {
            int v = wtot[lane];
#pragma unroll
            for (int off = 1; off < 32; off <<= 1) {
                int t2 = __shfl_up_sync(0xffffffffu, v, off);
                if (lane >= off) v += t2;
            }
            wtot[lane] = v;
        }
        __syncthreads();
        const int total = wtot[31];
        K = min(K_PRE, total);
        if (tid == 0) s_K = K;
        if (K > 0) {
            int above = (ps2 - ssum) + (w > 0 ? wtot[w - 1] : 0);
            const int m = min(M_FAST, K);
#pragma unroll
            for (int t2 = 0; t2 < 2; t2++) {
                int r = (t2 == 0) ? m : K;
                if (above < r && r <= above + ssum) {
                    int cum = above;
#pragma unroll
                    for (int j = 0; j < BINS_PT; j++) {
                        if (cum + loc10[j] >= r) {
                            s_thr[t2] = bin_floor(NBINS - 1 - (tid * BINS_PT + j));
                            break;
                        }
                        cum += loc10[j];
                    }
                }
            }
        }
        __syncthreads();
    }
    K = s_K;
    const int gc = s_gc;
    const bool use_list = fine_ok && (s_thr[1] >= STATIC_CUT) && (gc > 0) && (gc <= GCAP);

    // ---- re-zero histogram (coalesced) + list counter for next run ----
    for (int i = tid; i < NBINS; i += NT) h[i] = 0;
    if (tid == 0) g_gcnt[b] = 0;

    const float4* sc4 = reinterpret_cast<const float4*>(g_maxs + (size_t)b * NA);
    const int N4 = NA / 4;
    int nfinal = 0;

    for (int round = 0; round < 2; round++) {
        const unsigned thr = s_thr[round];
        if (tid == 0) s_cnt = 0;
        __syncthreads();
        if (use_list) {
            const ull* lst = g_list + (size_t)b * GCAP;
            for (int i = tid; i < gc; i += NT) {
                ull key = lst[i];
                if ((unsigned)(key >> 32) >= thr) {
                    int pos = atomicAdd(&s_cnt, 1);
                    if (pos < CAND_CAP) buf[pos] = key;
                }
            }
        } else {
            for (int i = tid; i < N4; i += NT) {
                float4 v = sc4[i];
                unsigned kk[4] = { __float_as_uint(v.x), __float_as_uint(v.y),
                                   __float_as_uint(v.z), __float_as_uint(v.w) };
#pragma unroll
                for (int c = 0; c < 4; c++) {
                    if (kk[c] > THR_BITS && kk[c] >= thr) {
                        int pos = atomicAdd(&s_cnt, 1);
                        int idx = i * 4 + c;
                        if (pos < CAND_CAP)
                            buf[pos] = ((ull)kk[c] << 32) |
                                       ((ull)(0xFFFFu - (unsigned)idx) << 16) |
                                       (ull)g_cls[(size_t)b * NA + idx];
                    }
                }
            }
        }
        __syncthreads();
        const int n = min(s_cnt, CAND_CAP);
        if (round == 0 && n > 1024) continue;

        int SZ = 32;
        while (SZ < n) SZ <<= 1;
        const int L = min(K, n);
        for (int i = n + tid; i < SZ; i += NT) buf[i] = 0ULL;
        __syncthreads();

        // ---- bitonic sort (descending, SZ keys) ----
        for (int k2 = 2; k2 <= SZ; k2 <<= 1) {
            for (int j = k2 >> 1; j >= 32; j >>= 1) {
                for (int t2 = tid; t2 < (SZ >> 1); t2 += NT) {
                    int i = ((t2 & ~(j - 1)) << 1) | (t2 & (j - 1));
                    int ixj = i + j;
                    bool desc = ((i & k2) == 0);
                    ull a = buf[i], c2 = buf[ixj];
                    if (desc ? (a < c2) : (a > c2)) { buf[i] = c2; buf[ixj] = a; }
                }
                __syncthreads();
            }
            const int jstart = min(k2 >> 1, 16);
            for (int e = tid; e < SZ; e += NT) {
                ull v = buf[e];
                bool desc = ((e & k2) == 0);
                for (int j = jstart; j; j >>= 1) {
                    ull o = __shfl_xor_sync(0xffffffffu, v, j);
                    bool lower = (lane & j) == 0;
                    if (desc == lower) v = (v > o) ? v : o;
                    else               v = (v < o) ? v : o;
                }
                buf[e] = v;
            }
            __syncthreads();
        }

        // ---- decode the first L candidates ----
        for (int i = tid; i < L; i += NT) {
            ull key = buf[i];
            unsigned idx = 0xFFFFu - (unsigned)((key >> 16) & 0xFFFFu);
            float score = __uint_as_float((unsigned)(key >> 32));
            float4 an = reinterpret_cast<const float4*>(anchors)[idx];
            float4 lp = reinterpret_cast<const float4*>(loc)[(size_t)b * NA + idx];
            float ya = (an.x + an.z) * 0.5f, xa = (an.y + an.w) * 0.5f;
            float ha = an.z - an.x, wa = an.w - an.y;
            float hh = expf(lp.z) * ha;
            float ww = expf(lp.w) * wa;
            float yc = lp.x * ha + ya;
            float xc = lp.y * wa + xa;
            float x1 = fminf(fmaxf(xc - 0.5f * ww, 0.f), IMGF);
            float y1 = fminf(fmaxf(yc - 0.5f * hh, 0.f), IMGF);
            float x2 = fminf(fmaxf(xc + 0.5f * ww, 0.f), IMGF);
            float y2 = fminf(fmaxf(yc + 0.5f * hh, 0.f), IMGF);
            sbox[i] = make_float4(x1, y1, x2, y2);
            sval[i] = score;
            scls[i] = (int)(key & 0xFFFFu);
        }
        __syncthreads();   // keys in buf now dead; adj reuses the space

        // ---- class-bucketed adjacency for top MC candidates ----
        const int MC = min(L, 256);
        for (int i = tid; i < 2048; i += NT) adj[i] = 0;
        if (tid < 96) s_ccnt[tid] = 0;
        __syncthreads();
        for (int i = tid; i < MC; i += NT) atomicAdd(&s_ccnt[scls[i]], 1);
        __syncthreads();
        if (w == 0) {   // prefix over 96 counters: lane l owns classes 3l..3l+2
            int base = lane * 3;
            int c0 = s_ccnt[base], c1 = s_ccnt[base + 1], c2 = s_ccnt[base + 2];
            int ssum2 = c0 + c1 + c2;
            int pre = ssum2;
#pragma unroll
            for (int off = 1; off < 32; off <<= 1) {
                int t2 = __shfl_up_sync(0xffffffffu, pre, off);
                if (lane >= off) pre += t2;
            }
            int st = pre - ssum2;
            s_cstart[base] = st;
            s_cstart[base + 1] = st + c0;
            s_cstart[base + 2] = st + c0 + c1;
            s_coff[base] = st;
            s_coff[base + 1] = st + c0;
            s_coff[base + 2] = st + c0 + c1;
        }
        __syncthreads();
        for (int i = tid; i < MC; i += NT) {
            int pos = atomicAdd(&s_coff[scls[i]], 1);
            s_clist[pos] = (short)i;
        }
        __syncthreads();
        // same-class pairs only
        for (int p = tid; p < MC; p += NT) {
            int a = s_clist[p];
            int c = scls[a];
            int end = s_cstart[c] + s_ccnt[c];
            float4 ba = sbox[a];
            float aa = (ba.z - ba.x) * (ba.w - ba.y);
            for (int q2 = p + 1; q2 < end; q2++) {
                int bc = s_clist[q2];
                float4 bb = sbox[bc];
                float xx1 = fmaxf(ba.x, bb.x), yy1 = fmaxf(ba.y, bb.y);
                float xx2 = fminf(ba.z, bb.z), yy2 = fminf(ba.w, bb.w);
                float in = fmaxf(xx2 - xx1, 0.f) * fmaxf(yy2 - yy1, 0.f);
                float ab = (bb.z - bb.x) * (bb.w - bb.y);
                if (in > IOU_THR * (aa + ab - in + 1e-8f)) {
                    int i = min(a, bc), j = max(a, bc);
                    atomicOr(&adj[i * 8 + (j >> 5)], 1u << (j & 31));
                }
            }
        }
        if (tid == 0) s_nk = 0;
        __syncthreads();

        // ---- greedy scan over bitmask (warp 0) ----
        if (tid < 32) {
            unsigned sup = 0;
            int nk = 0;
            for (int i = 0; i < MC && nk < K_OUT; i++) {
                unsigned sb = (lane == (i >> 5)) ? ((sup >> (i & 31)) & 1u) : 0u;
                if (__ballot_sync(0xffffffffu, sb != 0u) == 0u) {
                    if (lane < 8) sup |= adj[i * 8 + lane];
                    if (lane == 0) kept[nk] = (short)i;
                    nk++;
                }
            }
            for (int s2 = lane; s2 < nk; s2 += 32) {
                int ki = kept[s2];
                float4 bb = sbox[ki];
                kbox[s2] = bb;
                karea[s2] = (bb.z - bb.x) * (bb.w - bb.y);
                kcls[s2] = scls[ki];
            }
            __syncwarp();
            for (int i2 = MC; i2 < L && nk < K_OUT; i2++) {
                float4 bi = sbox[i2];
                int ci = scls[i2];
                float ai = (bi.z - bi.x) * (bi.w - bi.y);
                bool sup2 = false;
#pragma unroll
                for (int r = 0; r < 4; r++) {
                    int slot = lane + (r << 5);
                    if (slot < nk && kcls[slot] == ci) {
                        float4 bj = kbox[slot];
                        float xx1 = fmaxf(bi.x, bj.x), yy1 = fmaxf(bi.y, bj.y);
                        float xx2 = fminf(bi.z, bj.z), yy2 = fminf(bi.w, bj.w);
                        float in = fmaxf(xx2 - xx1, 0.f) * fmaxf(yy2 - yy1, 0.f);
                        if (in > IOU_THR * (ai + karea[slot] - in + 1e-8f)) sup2 = true;
                    }
                }
                if (__ballot_sync(0xffffffffu, sup2) == 0u) {
                    if (lane == 0) {
                        kbox[nk] = bi; karea[nk] = ai; kcls[nk] = ci; kept[nk] = (short)i2;
                    }
                    __syncwarp();
                    nk++;
                }
            }
            if (lane == 0) s_nk = nk;
        }
        __syncthreads();
        nfinal = s_nk;
        if (round == 1 || nfinal >= K_OUT || n >= K) break;
    }

    const int nk = nfinal;
    float* oboxes  = out + (size_t)b * K_OUT * 4;
    float* oscores = out + (size_t)NB * K_OUT * 4 + (size_t)b * K_OUT;
    float* olabels = out + (size_t)NB * K_OUT * 5 + (size_t)b * K_OUT;
    for (int s2 = tid; s2 < K_OUT; s2 += NT) {
        if (s2 < nk) {
            int i = kept[s2];
            float4 bb = sbox[i];
            oboxes[s2 * 4 + 0] = bb.x;
            oboxes[s2 * 4 + 1] = bb.y;
            oboxes[s2 * 4 + 2] = bb.z;
            oboxes[s2 * 4 + 3] = bb.w;
            oscores[s2] = sval[i];
            olabels[s2] = (float)scls[i];
        } else {
            oboxes[s2 * 4 + 0] = 0.f;
            oboxes[s2 * 4 + 1] = 0.f;
            oboxes[s2 * 4 + 2] = 1.f;
            oboxes[s2 * 4 + 3] = 1.f;
            oscores[s2] = 0.f;
            olabels[s2] = -1.f;
        }
    }
}

// ---------------- launch ----------------
extern "C" void kernel_launch(void* const* d_in, const int* in_sizes, int n_in,
                              void* d_out, int out_size) {
    const float* cls     = (const float*)d_in[0];
    const float* loc     = (const float*)d_in[1];
    const float* anchors = (const float*)d_in[2];
    float* out = (float*)d_out;

    k_maxarg<<<NROW / TR, 512>>>(cls);    // 3069 blocks x 512 threads (4/row)
    k_fused<<<NB, 1024>>>(loc, anchors, out);
}

// round 14
// speedup vs baseline: 1.0204x; 1.0204x over previous
#include <cuda_runtime.h>
#include <cstdint>

#define NB 8
#define NA 49104
#define NC 90
#define IMGF 512.0f
#define SCORE_THR 0.2f
#define THR_BITS 0x3E4CCCCDu   /* bits of 0.2f; valid <=> bits > THR_BITS */
#define FINE_CUT 0x3F7F0000u   /* ~0.99609: fine-bin region start */
#define STATIC_CUT 0x3F7FE000u /* fine bin 896; list pre-filter cut (~0.99951) */
#define NCOARSE 9799
#define NFINE 1024
#define NBINS (NCOARSE + NFINE)   /* 10823 */
#define BINS_PT 11
#define IOU_THR 0.2f
#define K_PRE 1000
#define K_OUT 100
#define NROW (NB * NA)
#define CAND_CAP 2048
#define M_FAST 192
#define GCAP 4096
#define TR 128                  /* rows per k_maxarg block */

typedef unsigned long long ull;

// -------- scratch (zero-init at load; k_fused re-zeroes g_hist/g_gcnt) -----
__device__ float g_maxs[NROW];
__device__ int g_hist[NB * NBINS];
__device__ int g_gcnt[NB];
__device__ ull g_list[NB * GCAP];

__device__ __forceinline__ unsigned bin_floor(int bin) {
    return (bin >= NCOARSE) ? FINE_CUT + ((unsigned)(bin - NCOARSE) << 6)
                            : THR_BITS + ((unsigned)bin << 11);
}

// ---- K1: coalesced smem staging + thread-per-row FMNMX reduce -------------
__global__ void __launch_bounds__(TR) k_maxarg(const float* __restrict__ cls) {
    __shared__ float s[TR * NC];                  // 46080 B static
    const int blk = blockIdx.x, tid = threadIdx.x;

    // stage 128 rows (2880 float4) fully coalesced
    const float4* src = reinterpret_cast<const float4*>(cls + (size_t)blk * TR * NC);
    float4* dst = reinterpret_cast<float4*>(s);
#pragma unroll
    for (int i = 0; i < 22; i++) dst[tid + i * TR] = src[tid + i * TR];
    if (tid < 64) dst[tid + 22 * TR] = src[tid + 22 * TR];
    __syncthreads();

    // reduce: thread tid owns row tid — pure fmaxf chains (scores positive)
    const float* rp = s + tid * NC;
    const float2* p = reinterpret_cast<const float2*>(rp);
    float m0 = 0.f, m1 = 0.f, m2 = 0.f, m3 = 0.f;
#pragma unroll
    for (int i = 0; i < 22; i++) {
        float2 a = p[2 * i];
        float2 b = p[2 * i + 1];
        m0 = fmaxf(m0, a.x);
        m1 = fmaxf(m1, a.y);
        m2 = fmaxf(m2, b.x);
        m3 = fmaxf(m3, b.y);
    }
    {
        float2 a = p[44];
        m0 = fmaxf(m0, a.x);
        m1 = fmaxf(m1, a.y);
    }
    float mxf = fmaxf(fmaxf(m0, m1), fmaxf(m2, m3));
    unsigned mx = __float_as_uint(mxf);

    const int row = blk * TR + tid;
    g_maxs[row] = mxf;
    if (mx > THR_BITS) {
        int b = row / NA;
        unsigned bin = (mx >= FINE_CUT)
                         ? (unsigned)NCOARSE + min((mx - FINE_CUT) >> 6, (unsigned)(NFINE - 1))
                         : (mx - THR_BITS) >> 11;
        atomicAdd(&g_hist[b * NBINS + bin], 1);
        if (mx >= STATIC_CUT) {
            // rare (~4%): recover exact first-argmax by bit equality
            int bi = 0;
            for (int j = 0; j < NC; j++)
                if (__float_as_uint(rp[j]) == mx) { bi = j; break; }
            int idx = row - b * NA;
            int pos = atomicAdd(&g_gcnt[b], 1);
            if (pos < GCAP)
                g_list[b * GCAP + pos] = ((ull)mx << 32) |
                                         ((ull)(0xFFFFu - (unsigned)idx) << 16) | (ull)bi;
        }
    }
}

// ---------------- K2: fused thresholds + compact + sort + bucketed NMS -----
__global__ void __launch_bounds__(1024, 1)
k_fused(const float* __restrict__ cls,
        const float* __restrict__ loc,
        const float* __restrict__ anchors,
        float* __restrict__ out) {
    const int b = blockIdx.x;
    const int tid = threadIdx.x;
    const int lane = tid & 31, w = tid >> 5;
    const int NT = 1024;

    __shared__ ull buf[CAND_CAP];           // sort keys; reused as adj after decode
    __shared__ float4 sbox[1024];
    __shared__ float sval[1024];
    __shared__ int scls[1024];
    __shared__ float4 kbox[K_OUT];
    __shared__ float karea[K_OUT];
    __shared__ int kcls[K_OUT];
    __shared__ short kept[K_OUT];
    __shared__ int wtot[32];
    __shared__ int s_nk, s_cnt, s_gc, s_K;
    __shared__ unsigned s_thr[2];
    __shared__ int s_ccnt[96], s_cstart[96], s_coff[96];
    __shared__ short s_clist[256];

    unsigned* adj = reinterpret_cast<unsigned*>(buf);   // adj[i*8 + word], 256x8

    int* h = g_hist + b * NBINS;
    if (tid == 0) {
        s_gc = g_gcnt[b];
        s_thr[0] = 0xFFFFFFFFu; s_thr[1] = 0xFFFFFFFFu;
        s_nk = 0; s_K = 0;
    }

    // ---- fast threshold pass: fine region only, coalesced ----
    int fineval = h[NBINS - 1 - tid];       // tid t owns fine bin NBINS-1-t (desc)
    int ps = fineval;
#pragma unroll
    for (int off = 1; off < 32; off <<= 1) {
        int t2 = __shfl_up_sync(0xffffffffu, ps, off);
        if (lane >= off) ps += t2;
    }
    if (lane == 31) wtot[w] = ps;
    __syncthreads();
    if (w == 0) {
        int v = wtot[lane];
#pragma unroll
        for (int off = 1; off < 32; off <<= 1) {
            int t2 = __shfl_up_sync(0xffffffffu, v, off);
            if (lane >= off) v += t2;
        }
        wtot[lane] = v;
    }
    __syncthreads();
    const int fine_total = wtot[31];
    bool fine_ok = (fine_total >= K_PRE);
    int K;
    if (fine_ok) {
        K = K_PRE;
        int above = (ps - fineval) + (w > 0 ? wtot[w - 1] : 0);
        const int m = M_FAST;
#pragma unroll
        for (int t2 = 0; t2 < 2; t2++) {
            int r = (t2 == 0) ? m : K_PRE;
            if (above < r && r <= above + fineval)
                s_thr[t2] = FINE_CUT + ((unsigned)(1023 - tid) << 6);
        }
        if (tid == 0) s_K = K_PRE;
        __syncthreads();
    } else {
        __syncthreads();
        int loc10[BINS_PT];
        int ssum = 0;
#pragma unroll
        for (int j = 0; j < BINS_PT; j++) {
            int bi = NBINS - 1 - (tid * BINS_PT + j);
            loc10[j] = (bi >= 0) ? h[bi] : 0;
            ssum += loc10[j];
        }
        int ps2 = ssum;
#pragma unroll
        for (int off = 1; off < 32; off <<= 1) {
            int t2 = __shfl_up_sync(0xffffffffu, ps2, off);
            if (lane >= off) ps2 += t2;
        }
        if (lane == 31) wtot[w] = ps2;
        __syncthreads();
        if (w == 0) {
            int v = wtot[lane];
#pragma unroll
            for (int off = 1; off < 32; off <<= 1) {
                int t2 = __shfl_up_sync(0xffffffffu, v, off);
                if (lane >= off) v += t2;
            }
            wtot[lane] = v;
        }
        __syncthreads();
        const int total = wtot[31];
        K = min(K_PRE, total);
        if (tid == 0) s_K = K;
        if (K > 0) {
            int above = (ps2 - ssum) + (w > 0 ? wtot[w - 1] : 0);
            const int m = min(M_FAST, K);
#pragma unroll
            for (int t2 = 0; t2 < 2; t2++) {
                int r = (t2 == 0) ? m : K;
                if (above < r && r <= above + ssum) {
                    int cum = above;
#pragma unroll
                    for (int j = 0; j < BINS_PT; j++) {
                        if (cum + loc10[j] >= r) {
                            s_thr[t2] = bin_floor(NBINS - 1 - (tid * BINS_PT + j));
                            break;
                        }
                        cum += loc10[j];
                    }
                }
            }
        }
        __syncthreads();
    }
    K = s_K;
    const int gc = s_gc;
    const bool use_list = fine_ok && (s_thr[1] >= STATIC_CUT) && (gc > 0) && (gc <= GCAP);

    // ---- re-zero histogram (coalesced) + list counter for next run ----
    for (int i = tid; i < NBINS; i += NT) h[i] = 0;
    if (tid == 0) g_gcnt[b] = 0;

    const float4* sc4 = reinterpret_cast<const float4*>(g_maxs + (size_t)b * NA);
    const int N4 = NA / 4;
    int nfinal = 0;

    for (int round = 0; round < 2; round++) {
        const unsigned thr = s_thr[round];
        if (tid == 0) s_cnt = 0;
        __syncthreads();
        if (use_list) {
            const ull* lst = g_list + (size_t)b * GCAP;
            for (int i = tid; i < gc; i += NT) {
                ull key = lst[i];
                if ((unsigned)(key >> 32) >= thr) {
                    int pos = atomicAdd(&s_cnt, 1);
                    if (pos < CAND_CAP) buf[pos] = key;
                }
            }
        } else {
            // fallback: rescan maxima; recompute class from cls (g_cls removed)
            for (int i = tid; i < N4; i += NT) {
                float4 v = sc4[i];
                unsigned kk[4] = { __float_as_uint(v.x), __float_as_uint(v.y),
                                   __float_as_uint(v.z), __float_as_uint(v.w) };
#pragma unroll
                for (int c = 0; c < 4; c++) {
                    if (kk[c] > THR_BITS && kk[c] >= thr) {
                        int pos = atomicAdd(&s_cnt, 1);
                        int idx = i * 4 + c;
                        if (pos < CAND_CAP) {
                            const float* rp = cls + ((size_t)b * NA + idx) * NC;
                            int bi = 0;
                            for (int j = 0; j < NC; j++)
                                if (__float_as_uint(rp[j]) == kk[c]) { bi = j; break; }
                            buf[pos] = ((ull)kk[c] << 32) |
                                       ((ull)(0xFFFFu - (unsigned)idx) << 16) |
                                       (ull)bi;
                        }
                    }
                }
            }
        }
        __syncthreads();
        const int n = min(s_cnt, CAND_CAP);
        if (round == 0 && n > 1024) continue;

        int SZ = 32;
        while (SZ < n) SZ <<= 1;
        const int L = min(K, n);
        for (int i = n + tid; i < SZ; i += NT) buf[i] = 0ULL;
        __syncthreads();

        // ---- bitonic sort (descending, SZ keys) ----
        for (int k2 = 2; k2 <= SZ; k2 <<= 1) {
            for (int j = k2 >> 1; j >= 32; j >>= 1) {
                for (int t2 = tid; t2 < (SZ >> 1); t2 += NT) {
                    int i = ((t2 & ~(j - 1)) << 1) | (t2 & (j - 1));
                    int ixj = i + j;
                    bool desc = ((i & k2) == 0);
                    ull a = buf[i], c2 = buf[ixj];
                    if (desc ? (a < c2) : (a > c2)) { buf[i] = c2; buf[ixj] = a; }
                }
                __syncthreads();
            }
            const int jstart = min(k2 >> 1, 16);
            for (int e = tid; e < SZ; e += NT) {
                ull v = buf[e];
                bool desc = ((e & k2) == 0);
                for (int j = jstart; j; j >>= 1) {
                    ull o = __shfl_xor_sync(0xffffffffu, v, j);
                    bool lower = (lane & j) == 0;
                    if (desc == lower) v = (v > o) ? v : o;
                    else               v = (v < o) ? v : o;
                }
                buf[e] = v;
            }
            __syncthreads();
        }

        // ---- decode the first L candidates ----
        for (int i = tid; i < L; i += NT) {
            ull key = buf[i];
            unsigned idx = 0xFFFFu - (unsigned)((key >> 16) & 0xFFFFu);
            float score = __uint_as_float((unsigned)(key >> 32));
            float4 an = reinterpret_cast<const float4*>(anchors)[idx];
            float4 lp = reinterpret_cast<const float4*>(loc)[(size_t)b * NA + idx];
            float ya = (an.x + an.z) * 0.5f, xa = (an.y + an.w) * 0.5f;
            float ha = an.z - an.x, wa = an.w - an.y;
            float hh = expf(lp.z) * ha;
            float ww = expf(lp.w) * wa;
            float yc = lp.x * ha + ya;
            float xc = lp.y * wa + xa;
            float x1 = fminf(fmaxf(xc - 0.5f * ww, 0.f), IMGF);
            float y1 = fminf(fmaxf(yc - 0.5f * hh, 0.f), IMGF);
            float x2 = fminf(fmaxf(xc + 0.5f * ww, 0.f), IMGF);
            float y2 = fminf(fmaxf(yc + 0.5f * hh, 0.f), IMGF);
            sbox[i] = make_float4(x1, y1, x2, y2);
            sval[i] = score;
            scls[i] = (int)(key & 0xFFFFu);
        }
        __syncthreads();   // keys in buf now dead; adj reuses the space

        // ---- class-bucketed adjacency for top MC candidates ----
        const int MC = min(L, 256);
        for (int i = tid; i < 2048; i += NT) adj[i] = 0;
        if (tid < 96) s_ccnt[tid] = 0;
        __syncthreads();
        for (int i = tid; i < MC; i += NT) atomicAdd(&s_ccnt[scls[i]], 1);
        __syncthreads();
        if (w == 0) {   // prefix over 96 counters: lane l owns classes 3l..3l+2
            int base = lane * 3;
            int c0 = s_ccnt[base], c1 = s_ccnt[base + 1], c2 = s_ccnt[base + 2];
            int ssum2 = c0 + c1 + c2;
            int pre = ssum2;
#pragma unroll
            for (int off = 1; off < 32; off <<= 1) {
                int t2 = __shfl_up_sync(0xffffffffu, pre, off);
                if (lane >= off) pre += t2;
            }
            int st = pre - ssum2;
            s_cstart[base] = st;
            s_cstart[base + 1] = st + c0;
            s_cstart[base + 2] = st + c0 + c1;
            s_coff[base] = st;
            s_coff[base + 1] = st + c0;
            s_coff[base + 2] = st + c0 + c1;
        }
        __syncthreads();
        for (int i = tid; i < MC; i += NT) {
            int pos = atomicAdd(&s_coff[scls[i]], 1);
            s_clist[pos] = (short)i;
        }
        __syncthreads();
        // same-class pairs only
        for (int p = tid; p < MC; p += NT) {
            int a = s_clist[p];
            int c = scls[a];
            int end = s_cstart[c] + s_ccnt[c];
            float4 ba = sbox[a];
            float aa = (ba.z - ba.x) * (ba.w - ba.y);
            for (int q2 = p + 1; q2 < end; q2++) {
                int bc = s_clist[q2];
                float4 bb = sbox[bc];
                float xx1 = fmaxf(ba.x, bb.x), yy1 = fmaxf(ba.y, bb.y);
                float xx2 = fminf(ba.z, bb.z), yy2 = fminf(ba.w, bb.w);
                float in = fmaxf(xx2 - xx1, 0.f) * fmaxf(yy2 - yy1, 0.f);
                float ab = (bb.z - bb.x) * (bb.w - bb.y);
                if (in > IOU_THR * (aa + ab - in + 1e-8f)) {
                    int i = min(a, bc), j = max(a, bc);
                    atomicOr(&adj[i * 8 + (j >> 5)], 1u << (j & 31));
                }
            }
        }
        if (tid == 0) s_nk = 0;
        __syncthreads();

        // ---- greedy scan over bitmask (warp 0) ----
        if (tid < 32) {
            unsigned sup = 0;
            int nk = 0;
            for (int i = 0; i < MC && nk < K_OUT; i++) {
                unsigned sb = (lane == (i >> 5)) ? ((sup >> (i & 31)) & 1u) : 0u;
                if (__ballot_sync(0xffffffffu, sb != 0u) == 0u) {
                    if (lane < 8) sup |= adj[i * 8 + lane];
                    if (lane == 0) kept[nk] = (short)i;
                    nk++;
                }
            }
            for (int s2 = lane; s2 < nk; s2 += 32) {
                int ki = kept[s2];
                float4 bb = sbox[ki];
                kbox[s2] = bb;
                karea[s2] = (bb.z - bb.x) * (bb.w - bb.y);
                kcls[s2] = scls[ki];
            }
            __syncwarp();
            for (int i2 = MC; i2 < L && nk < K_OUT; i2++) {
                float4 bi = sbox[i2];
                int ci = scls[i2];
                float ai = (bi.z - bi.x) * (bi.w - bi.y);
                bool sup2 = false;
#pragma unroll
                for (int r = 0; r < 4; r++) {
                    int slot = lane + (r << 5);
                    if (slot < nk && kcls[slot] == ci) {
                        float4 bj = kbox[slot];
                        float xx1 = fmaxf(bi.x, bj.x), yy1 = fmaxf(bi.y, bj.y);
                        float xx2 = fminf(bi.z, bj.z), yy2 = fminf(bi.w, bj.w);
                        float in = fmaxf(xx2 - xx1, 0.f) * fmaxf(yy2 - yy1, 0.f);
                        if (in > IOU_THR * (ai + karea[slot] - in + 1e-8f)) sup2 = true;
                    }
                }
                if (__ballot_sync(0xffffffffu, sup2) == 0u) {
                    if (lane == 0) {
                        kbox[nk] = bi; karea[nk] = ai; kcls[nk] = ci; kept[nk] = (short)i2;
                    }
                    __syncwarp();
                    nk++;
                }
            }
            if (lane == 0) s_nk = nk;
        }
        __syncthreads();
        nfinal = s_nk;
        if (round == 1 || nfinal >= K_OUT || n >= K) break;
    }

    const int nk = nfinal;
    float* oboxes  = out + (size_t)b * K_OUT * 4;
    float* oscores = out + (size_t)NB * K_OUT * 4 + (size_t)b * K_OUT;
    float* olabels = out + (size_t)NB * K_OUT * 5 + (size_t)b * K_OUT;
    for (int s2 = tid; s2 < K_OUT; s2 += NT) {
        if (s2 < nk) {
            int i = kept[s2];
            float4 bb = sbox[i];
            oboxes[s2 * 4 + 0] = bb.x;
            oboxes[s2 * 4 + 1] = bb.y;
            oboxes[s2 * 4 + 2] = bb.z;
            oboxes[s2 * 4 + 3] = bb.w;
            oscores[s2] = sval[i];
            olabels[s2] = (float)scls[i];
        } else {
            oboxes[s2 * 4 + 0] = 0.f;
            oboxes[s2 * 4 + 1] = 0.f;
            oboxes[s2 * 4 + 2] = 1.f;
            oboxes[s2 * 4 + 3] = 1.f;
            oscores[s2] = 0.f;
            olabels[s2] = -1.f;
        }
    }
}

// ---------------- launch ----------------
extern "C" void kernel_launch(void* const* d_in, const int* in_sizes, int n_in,
                              void* d_out, int out_size) {
    const float* cls     = (const float*)d_in[0];
    const float* loc     = (const float*)d_in[1];
    const float* anchors = (const float*)d_in[2];
    float* out = (float*)d_out;

    k_maxarg<<<NROW / TR, TR>>>(cls);     // 3069 blocks x 128 threads
    k_fused<<<NB, 1024>>>(cls, loc, anchors, out);
}

// round 15
// speedup vs baseline: 1.0661x; 1.0447x over previous
#include <cuda_runtime.h>
#include <cstdint>

#define NB 8
#define NA 49104
#define NC 90
#define IMGF 512.0f
#define SCORE_THR 0.2f
#define THR_BITS 0x3E4CCCCDu   /* bits of 0.2f; valid <=> bits > THR_BITS */
#define FINE_CUT 0x3F7F0000u   /* ~0.99609: fine-bin region start */
#define STATIC_CUT 0x3F7FE000u /* fine bin 896; list pre-filter cut (~0.99951) */
#define NCOARSE 9799
#define NFINE 1024
#define NBINS (NCOARSE + NFINE)   /* 10823 */
#define BINS_PT 11
#define IOU_THR 0.2f
#define K_PRE 1000
#define K_OUT 100
#define NROW (NB * NA)
#define CAND_CAP 2048
#define M_FAST 192
#define GCAP 4096
#define TR 128                  /* rows per k_maxarg block */
#define TILE_BYTES (TR * NC * 4)   /* 46080 */

typedef unsigned long long ull;

// -------- scratch (zero-init at load; k_fused re-zeroes g_hist/g_gcnt) -----
__device__ float g_maxs[NROW];
__device__ int g_hist[NB * NBINS];
__device__ int g_gcnt[NB];
__device__ ull g_list[NB * GCAP];

__device__ __forceinline__ unsigned bin_floor(int bin) {
    return (bin >= NCOARSE) ? FINE_CUT + ((unsigned)(bin - NCOARSE) << 6)
                            : THR_BITS + ((unsigned)bin << 11);
}

__device__ __forceinline__ unsigned smem_u32(const void* p) {
    unsigned r;
    asm("{ .reg .u64 t; cvta.to.shared.u64 t, %1; cvt.u32.u64 %0, t; }"
        : "=r"(r) : "l"(p));
    return r;
}

// ---- K1: TMA bulk load to smem + thread-per-row FMNMX reduce --------------
__global__ void __launch_bounds__(TR) k_maxarg(const float* __restrict__ cls) {
    __shared__ alignas(16) float s[TR * NC];      // 46080 B
    __shared__ alignas(8) ull mb;
    const int blk = blockIdx.x, tid = threadIdx.x;
    const unsigned mbar = smem_u32(&mb);

    if (tid == 0)
        asm volatile("mbarrier.init.shared.b64 [%0], %1;"
                     :: "r"(mbar), "r"(1u) : "memory");
    __syncthreads();
    if (tid == 0) {
        asm volatile("mbarrier.arrive.expect_tx.shared.b64 _, [%0], %1;"
                     :: "r"(mbar), "r"((unsigned)TILE_BYTES) : "memory");
        asm volatile("cp.async.bulk.shared::cta.global.mbarrier::complete_tx::bytes "
                     "[%0], [%1], %2, [%3];"
                     :: "r"(smem_u32(s)),
                        "l"(cls + (size_t)blk * TR * NC),
                        "r"((unsigned)TILE_BYTES), "r"(mbar) : "memory");
    }
    // all threads wait (parity 0, acquire)
    {
        unsigned done = 0;
        while (!done)
            asm volatile("{ .reg .pred p; "
                         "mbarrier.try_wait.parity.acquire.cta.shared::cta.b64 p, [%1], %2; "
                         "selp.b32 %0, 1, 0, p; }"
                         : "=r"(done) : "r"(mbar), "r"(0u) : "memory");
    }

    // reduce: thread tid owns row tid — pure fmaxf chains (scores positive)
    const float* rp = s + tid * NC;
    const float2* p = reinterpret_cast<const float2*>(rp);
    float m0 = 0.f, m1 = 0.f, m2 = 0.f, m3 = 0.f;
#pragma unroll
    for (int i = 0; i < 22; i++) {
        float2 a = p[2 * i];
        float2 b = p[2 * i + 1];
        m0 = fmaxf(m0, a.x);
        m1 = fmaxf(m1, a.y);
        m2 = fmaxf(m2, b.x);
        m3 = fmaxf(m3, b.y);
    }
    {
        float2 a = p[44];
        m0 = fmaxf(m0, a.x);
        m1 = fmaxf(m1, a.y);
    }
    float mxf = fmaxf(fmaxf(m0, m1), fmaxf(m2, m3));
    unsigned mx = __float_as_uint(mxf);

    const int row = blk * TR + tid;
    g_maxs[row] = mxf;
    if (mx > THR_BITS) {
        int b = row / NA;
        unsigned bin = (mx >= FINE_CUT)
                         ? (unsigned)NCOARSE + min((mx - FINE_CUT) >> 6, (unsigned)(NFINE - 1))
                         : (mx - THR_BITS) >> 11;
        atomicAdd(&g_hist[b * NBINS + bin], 1);
        if (mx >= STATIC_CUT) {
            // rare (~4%): recover exact first-argmax by bit equality
            int bi = 0;
            for (int j = 0; j < NC; j++)
                if (__float_as_uint(rp[j]) == mx) { bi = j; break; }
            int idx = row - b * NA;
            int pos = atomicAdd(&g_gcnt[b], 1);
            if (pos < GCAP)
                g_list[b * GCAP + pos] = ((ull)mx << 32) |
                                         ((ull)(0xFFFFu - (unsigned)idx) << 16) | (ull)bi;
        }
    }
}

// ---------------- K2: fused thresholds + compact + sort + bucketed NMS -----
__global__ void __launch_bounds__(1024, 1)
k_fused(const float* __restrict__ cls,
        const float* __restrict__ loc,
        const float* __restrict__ anchors,
        float* __restrict__ out) {
    const int b = blockIdx.x;
    const int tid = threadIdx.x;
    const int lane = tid & 31, w = tid >> 5;
    const int NT = 1024;

    __shared__ ull buf[CAND_CAP];           // sort keys; reused as adj after decode
    __shared__ float4 sbox[1024];
    __shared__ float sval[1024];
    __shared__ int scls[1024];
    __shared__ float4 kbox[K_OUT];
    __shared__ float karea[K_OUT];
    __shared__ int kcls[K_OUT];
    __shared__ short kept[K_OUT];
    __shared__ int wtot[32];
    __shared__ int s_nk, s_cnt, s_gc, s_K;
    __shared__ unsigned s_thr[2];
    __shared__ int s_ccnt[96], s_cstart[96], s_coff[96];
    __shared__ short s_clist[256];

    unsigned* adj = reinterpret_cast<unsigned*>(buf);   // adj[i*8 + word], 256x8

    int* h = g_hist + b * NBINS;
    if (tid == 0) {
        s_gc = g_gcnt[b];
        s_thr[0] = 0xFFFFFFFFu; s_thr[1] = 0xFFFFFFFFu;
        s_nk = 0; s_K = 0;
    }

    // ---- fast threshold pass: fine region only, coalesced ----
    int fineval = h[NBINS - 1 - tid];       // tid t owns fine bin NBINS-1-t (desc)
    int ps = fineval;
#pragma unroll
    for (int off = 1; off < 32; off <<= 1) {
        int t2 = __shfl_up_sync(0xffffffffu, ps, off);
        if (lane >= off) ps += t2;
    }
    if (lane == 31) wtot[w] = ps;
    __syncthreads();
    if (w == 0) {
        int v = wtot[lane];
#pragma unroll
        for (int off = 1; off < 32; off <<= 1) {
            int t2 = __shfl_up_sync(0xffffffffu, v, off);
            if (lane >= off) v += t2;
        }
        wtot[lane] = v;
    }
    __syncthreads();
    const int fine_total = wtot[31];
    bool fine_ok = (fine_total >= K_PRE);
    int K;
    if (fine_ok) {
        K = K_PRE;
        int above = (ps - fineval) + (w > 0 ? wtot[w - 1] : 0);
        const int m = M_FAST;
#pragma unroll
        for (int t2 = 0; t2 < 2; t2++) {
            int r = (t2 == 0) ? m : K_PRE;
            if (above < r && r <= above + fineval)
                s_thr[t2] = FINE_CUT + ((unsigned)(1023 - tid) << 6);
        }
        if (tid == 0) s_K = K_PRE;
        __syncthreads();
    } else {
        __syncthreads();
        int loc10[BINS_PT];
        int ssum = 0;
#pragma unroll
        for (int j = 0; j < BINS_PT; j++) {
            int bi = NBINS - 1 - (tid * BINS_PT + j);
            loc10[j] = (bi >= 0) ? h[bi] : 0;
            ssum += loc10[j];
        }
        int ps2 = ssum;
#pragma unroll
        for (int off = 1; off < 32; off <<= 1) {
            int t2 = __shfl_up_sync(0xffffffffu, ps2, off);
            if (lane >= off) ps2 += t2;
        }
        if (lane == 31) wtot[w] = ps2;
        __syncthreads();
        if (w == 0) {
            int v = wtot[lane];
#pragma unroll
            for (int off = 1; off < 32; off <<= 1) {
                int t2 = __shfl_up_sync(0xffffffffu, v, off);
                if (lane >= off) v += t2;
            }
            wtot[lane] = v;
        }
        __syncthreads();
        const int total = wtot[31];
        K = min(K_PRE, total);
        if (tid == 0) s_K = K;
        if (K > 0) {
            int above = (ps2 - ssum) + (w > 0 ? wtot[w - 1] : 0);
            const int m = min(M_FAST, K);
#pragma unroll
            for (int t2 = 0; t2 < 2; t2++) {
                int r = (t2 == 0) ? m : K;
                if (above < r && r <= above + ssum) {
                    int cum = above;
#pragma unroll
                    for (int j = 0; j < BINS_PT; j++) {
                        if (cum + loc10[j] >= r) {
                            s_thr[t2] = bin_floor(NBINS - 1 - (tid * BINS_PT + j));
                            break;
                        }
                        cum += loc10[j];
                    }
                }
            }
        }
        __syncthreads();
    }
    K = s_K;
    const int gc = s_gc;
    const bool use_list = fine_ok && (s_thr[1] >= STATIC_CUT) && (gc > 0) && (gc <= GCAP);

    // ---- re-zero histogram (coalesced) + list counter for next run ----
    for (int i = tid; i < NBINS; i += NT) h[i] = 0;
    if (tid == 0) g_gcnt[b] = 0;

    const float4* sc4 = reinterpret_cast<const float4*>(g_maxs + (size_t)b * NA);
    const int N4 = NA / 4;
    int nfinal = 0;

    for (int round = 0; round < 2; round++) {
        const unsigned thr = s_thr[round];
        if (tid == 0) s_cnt = 0;
        __syncthreads();
        if (use_list) {
            const ull* lst = g_list + (size_t)b * GCAP;
            for (int i = tid; i < gc; i += NT) {
                ull key = lst[i];
                if ((unsigned)(key >> 32) >= thr) {
                    int pos = atomicAdd(&s_cnt, 1);
                    if (pos < CAND_CAP) buf[pos] = key;
                }
            }
        } else {
            // fallback: rescan maxima; recompute class from cls
            for (int i = tid; i < N4; i += NT) {
                float4 v = sc4[i];
                unsigned kk[4] = { __float_as_uint(v.x), __float_as_uint(v.y),
                                   __float_as_uint(v.z), __float_as_uint(v.w) };
#pragma unroll
                for (int c = 0; c < 4; c++) {
                    if (kk[c] > THR_BITS && kk[c] >= thr) {
                        int pos = atomicAdd(&s_cnt, 1);
                        int idx = i * 4 + c;
                        if (pos < CAND_CAP) {
                            const float* rp = cls + ((size_t)b * NA + idx) * NC;
                            int bi = 0;
                            for (int j = 0; j < NC; j++)
                                if (__float_as_uint(rp[j]) == kk[c]) { bi = j; break; }
                            buf[pos] = ((ull)kk[c] << 32) |
                                       ((ull)(0xFFFFu - (unsigned)idx) << 16) |
                                       (ull)bi;
                        }
                    }
                }
            }
        }
        __syncthreads();
        const int n = min(s_cnt, CAND_CAP);
        if (round == 0 && n > 1024) continue;

        int SZ = 32;
        while (SZ < n) SZ <<= 1;
        const int L = min(K, n);
        for (int i = n + tid; i < SZ; i += NT) buf[i] = 0ULL;
        __syncthreads();

        // ---- bitonic sort (descending, SZ keys) ----
        for (int k2 = 2; k2 <= SZ; k2 <<= 1) {
            for (int j = k2 >> 1; j >= 32; j >>= 1) {
                for (int t2 = tid; t2 < (SZ >> 1); t2 += NT) {
                    int i = ((t2 & ~(j - 1)) << 1) | (t2 & (j - 1));
                    int ixj = i + j;
                    bool desc = ((i & k2) == 0);
                    ull a = buf[i], c2 = buf[ixj];
                    if (desc ? (a < c2) : (a > c2)) { buf[i] = c2; buf[ixj] = a; }
                }
                __syncthreads();
            }
            const int jstart = min(k2 >> 1, 16);
            for (int e = tid; e < SZ; e += NT) {
                ull v = buf[e];
                bool desc = ((e & k2) == 0);
                for (int j = jstart; j; j >>= 1) {
                    ull o = __shfl_xor_sync(0xffffffffu, v, j);
                    bool lower = (lane & j) == 0;
                    if (desc == lower) v = (v > o) ? v : o;
                    else               v = (v < o) ? v : o;
                }
                buf[e] = v;
            }
            __syncthreads();
        }

        // ---- decode the first L candidates ----
        for (int i = tid; i < L; i += NT) {
            ull key = buf[i];
            unsigned idx = 0xFFFFu - (unsigned)((key >> 16) & 0xFFFFu);
            float score = __uint_as_float((unsigned)(key >> 32));
            float4 an = reinterpret_cast<const float4*>(anchors)[idx];
            float4 lp = reinterpret_cast<const float4*>(loc)[(size_t)b * NA + idx];
            float ya = (an.x + an.z) * 0.5f, xa = (an.y + an.w) * 0.5f;
            float ha = an.z - an.x, wa = an.w - an.y;
            float hh = expf(lp.z) * ha;
            float ww = expf(lp.w) * wa;
            float yc = lp.x * ha + ya;
            float xc = lp.y * wa + xa;
            float x1 = fminf(fmaxf(xc - 0.5f * ww, 0.f), IMGF);
            float y1 = fminf(fmaxf(yc - 0.5f * hh, 0.f), IMGF);
            float x2 = fminf(fmaxf(xc + 0.5f * ww, 0.f), IMGF);
            float y2 = fminf(fmaxf(yc + 0.5f * hh, 0.f), IMGF);
            sbox[i] = make_float4(x1, y1, x2, y2);
            sval[i] = score;
            scls[i] = (int)(key & 0xFFFFu);
        }
        __syncthreads();   // keys in buf now dead; adj reuses the space

        // ---- class-bucketed adjacency for top MC candidates ----
        const int MC = min(L, 256);
        for (int i = tid; i < 2048; i += NT) adj[i] = 0;
        if (tid < 96) s_ccnt[tid] = 0;
        __syncthreads();
        for (int i = tid; i < MC; i += NT) atomicAdd(&s_ccnt[scls[i]], 1);
        __syncthreads();
        if (w == 0) {   // prefix over 96 counters: lane l owns classes 3l..3l+2
            int base = lane * 3;
            int c0 = s_ccnt[base], c1 = s_ccnt[base + 1], c2 = s_ccnt[base + 2];
            int ssum2 = c0 + c1 + c2;
            int pre = ssum2;
#pragma unroll
            for (int off = 1; off < 32; off <<= 1) {
                int t2 = __shfl_up_sync(0xffffffffu, pre, off);
                if (lane >= off) pre += t2;
            }
            int st = pre - ssum2;
            s_cstart[base] = st;
            s_cstart[base + 1] = st + c0;
            s_cstart[base + 2] = st + c0 + c1;
            s_coff[base] = st;
            s_coff[base + 1] = st + c0;
            s_coff[base + 2] = st + c0 + c1;
        }
        __syncthreads();
        for (int i = tid; i < MC; i += NT) {
            int pos = atomicAdd(&s_coff[scls[i]], 1);
            s_clist[pos] = (short)i;
        }
        __syncthreads();
        // same-class pairs only
        for (int p = tid; p < MC; p += NT) {
            int a = s_clist[p];
            int c = scls[a];
            int end = s_cstart[c] + s_ccnt[c];
            float4 ba = sbox[a];
            float aa = (ba.z - ba.x) * (ba.w - ba.y);
            for (int q2 = p + 1; q2 < end; q2++) {
                int bc = s_clist[q2];
                float4 bb = sbox[bc];
                float xx1 = fmaxf(ba.x, bb.x), yy1 = fmaxf(ba.y, bb.y);
                float xx2 = fminf(ba.z, bb.z), yy2 = fminf(ba.w, bb.w);
                float in = fmaxf(xx2 - xx1, 0.f) * fmaxf(yy2 - yy1, 0.f);
                float ab = (bb.z - bb.x) * (bb.w - bb.y);
                if (in > IOU_THR * (aa + ab - in + 1e-8f)) {
                    int i = min(a, bc), j = max(a, bc);
                    atomicOr(&adj[i * 8 + (j >> 5)], 1u << (j & 31));
                }
            }
        }
        if (tid == 0) s_nk = 0;
        __syncthreads();

        // ---- greedy scan over bitmask (warp 0) ----
        if (tid < 32) {
            unsigned sup = 0;
            int nk = 0;
            for (int i = 0; i < MC && nk < K_OUT; i++) {
                unsigned sb = (lane == (i >> 5)) ? ((sup >> (i & 31)) & 1u) : 0u;
                if (__ballot_sync(0xffffffffu, sb != 0u) == 0u) {
                    if (lane < 8) sup |= adj[i * 8 + lane];
                    if (lane == 0) kept[nk] = (short)i;
                    nk++;
                }
            }
            for (int s2 = lane; s2 < nk; s2 += 32) {
                int ki = kept[s2];
                float4 bb = sbox[ki];
                kbox[s2] = bb;
                karea[s2] = (bb.z - bb.x) * (bb.w - bb.y);
                kcls[s2] = scls[ki];
            }
            __syncwarp();
            for (int i2 = MC; i2 < L && nk < K_OUT; i2++) {
                float4 bi = sbox[i2];
                int ci = scls[i2];
                float ai = (bi.z - bi.x) * (bi.w - bi.y);
                bool sup2 = false;
#pragma unroll
                for (int r = 0; r < 4; r++) {
                    int slot = lane + (r << 5);
                    if (slot < nk && kcls[slot] == ci) {
                        float4 bj = kbox[slot];
                        float xx1 = fmaxf(bi.x, bj.x), yy1 = fmaxf(bi.y, bj.y);
                        float xx2 = fminf(bi.z, bj.z), yy2 = fminf(bi.w, bj.w);
                        float in = fmaxf(xx2 - xx1, 0.f) * fmaxf(yy2 - yy1, 0.f);
                        if (in > IOU_THR * (ai + karea[slot] - in + 1e-8f)) sup2 = true;
                    }
                }
                if (__ballot_sync(0xffffffffu, sup2) == 0u) {
                    if (lane == 0) {
                        kbox[nk] = bi; karea[nk] = ai; kcls[nk] = ci; kept[nk] = (short)i2;
                    }
                    __syncwarp();
                    nk++;
                }
            }
            if (lane == 0) s_nk = nk;
        }
        __syncthreads();
        nfinal = s_nk;
        if (round == 1 || nfinal >= K_OUT || n >= K) break;
    }

    const int nk = nfinal;
    float* oboxes  = out + (size_t)b * K_OUT * 4;
    float* oscores = out + (size_t)NB * K_OUT * 4 + (size_t)b * K_OUT;
    float* olabels = out + (size_t)NB * K_OUT * 5 + (size_t)b * K_OUT;
    for (int s2 = tid; s2 < K_OUT; s2 += NT) {
        if (s2 < nk) {
            int i = kept[s2];
            float4 bb = sbox[i];
            oboxes[s2 * 4 + 0] = bb.x;
            oboxes[s2 * 4 + 1] = bb.y;
            oboxes[s2 * 4 + 2] = bb.z;
            oboxes[s2 * 4 + 3] = bb.w;
            oscores[s2] = sval[i];
            olabels[s2] = (float)scls[i];
        } else {
            oboxes[s2 * 4 + 0] = 0.f;
            oboxes[s2 * 4 + 1] = 0.f;
            oboxes[s2 * 4 + 2] = 1.f;
            oboxes[s2 * 4 + 3] = 1.f;
            oscores[s2] = 0.f;
            olabels[s2] = -1.f;
        }
    }
}

// ---------------- launch ----------------
extern "C" void kernel_launch(void* const* d_in, const int* in_sizes, int n_in,
                              void* d_out, int out_size) {
    const float* cls     = (const float*)d_in[0];
    const float* loc     = (const float*)d_in[1];
    const float* anchors = (const float*)d_in[2];
    float* out = (float*)d_out;

    k_maxarg<<<NROW / TR, TR>>>(cls);     // 3069 blocks x 128 threads, TMA load
    k_fused<<<NB, 1024>>>(cls, loc, anchors, out);
}